// round 2
// baseline (speedup 1.0000x reference)
#include <cuda_runtime.h>
#include <cuda_bf16.h>

// WaveletTransformer: 4-level Haar DWT immediately inverted by its exact IDWT.
// Orthogonal perfect reconstruction => output == input to ~1e-7 rel err.
// Optimal kernel = streaming HBM copy. This round: __ldcs/__stcs streaming
// cache policy (no L2 allocate for a 512MiB pass through a 126MB L2) +
// 4x batched LDG.128 per iteration for higher MLP, exact-shape fast path
// (n4 = 2^24 -> 2^19 threads x 32 float4, no bounds checks).

__global__ void __launch_bounds__(512)
copy_stream_exact(const float4* __restrict__ in, float4* __restrict__ out) {
    unsigned t = blockIdx.x * 512u + threadIdx.x;   // 2^19 threads total
    const unsigned stride = 1024u * 512u;           // 2^19
    #pragma unroll
    for (int j = 0; j < 8; j++) {
        float4 a0 = __ldcs(in + t);
        float4 a1 = __ldcs(in + t + stride);
        float4 a2 = __ldcs(in + t + 2u * stride);
        float4 a3 = __ldcs(in + t + 3u * stride);
        __stcs(out + t,               a0);
        __stcs(out + t + stride,      a1);
        __stcs(out + t + 2u * stride, a2);
        __stcs(out + t + 3u * stride, a3);
        t += 4u * stride;
    }
}

__global__ void __launch_bounds__(512, 2)
copy_stream_generic(const float4* __restrict__ in, float4* __restrict__ out, long long n4) {
    long long i = (long long)blockIdx.x * blockDim.x + threadIdx.x;
    long long stride = (long long)gridDim.x * blockDim.x;
    for (; i < n4; i += stride) {
        __stcs(out + i, __ldcs(in + i));
    }
}

__global__ void copy_tail_kernel(const float* __restrict__ in, float* __restrict__ out,
                                 long long start, long long n) {
    long long i = start + blockIdx.x * blockDim.x + threadIdx.x;
    if (i < n) out[i] = in[i];
}

extern "C" void kernel_launch(void* const* d_in, const int* in_sizes, int n_in,
                              void* d_out, int out_size) {
    const float* x = (const float*)d_in[0];
    float* out = (float*)d_out;
    long long n = (long long)out_size;          // expected 32*512*4096 = 67108864
    long long n4 = n >> 2;

    if (n4 == (1LL << 24) && (n & 3LL) == 0) {
        // Exact-shape fast path: 1024 blocks x 512 threads, 32 float4/thread.
        copy_stream_exact<<<1024, 512>>>((const float4*)x, (float4*)out);
        return;
    }

    const int threads = 512;
    int blocks = 148 * 2 * 4;
    long long needed = (n4 + threads - 1) / threads;
    if ((long long)blocks > needed) blocks = (int)needed;
    if (blocks < 1) blocks = 1;
    if (n4 > 0)
        copy_stream_generic<<<blocks, threads>>>((const float4*)x, (float4*)out, n4);

    long long tail_start = n4 << 2;
    if (tail_start < n) {
        long long tail = n - tail_start;
        copy_tail_kernel<<<(unsigned)((tail + 255) / 256), 256>>>(x, out, tail_start, n);
    }
}

// round 3
// speedup vs baseline: 1.0088x; 1.0088x over previous
#include <cuda_runtime.h>
#include <cuda_bf16.h>

// WaveletTransformer: 4-level Haar DWT immediately inverted by its exact IDWT.
// Orthogonal perfect reconstruction => output == input to ~1e-7 rel err
// (rel_err 9.57e-8 confirmed on hardware, threshold 1e-3).
// => optimal kernel is a pure 256MiB->256MiB device copy.
//
// R1 (SM float4 grid-stride copy):        6361 GB/s, kernel 76.9us
// R2 (+__ldcs/__stcs, 4x MLP batching):   6261 GB/s, kernel 77.6us  (neutral)
// Conclusion: SM LDG/STG path is at the DRAM read/write-turnaround floor.
// R3: route through the copy engine instead (cudaMemcpyAsync D2D graph node).
// CEs schedule longer read/write bursts and typically reach 85-92% of HBM
// peak on local D2D, vs ~80% for SM copies; also removes kernel-launch
// overhead from the graph.

extern "C" void kernel_launch(void* const* d_in, const int* in_sizes, int n_in,
                              void* d_out, int out_size) {
    const float* x = (const float*)d_in[0];
    float* out = (float*)d_out;
    size_t bytes = (size_t)out_size * sizeof(float);
    // Async D2D on the default (capture) stream: becomes a single memcpy node
    // in the captured graph. No allocation, no sync — capture-legal.
    cudaMemcpyAsync(out, x, bytes, cudaMemcpyDeviceToDevice, 0);
}

// round 4
// speedup vs baseline: 1.0276x; 1.0186x over previous
#include <cuda_runtime.h>
#include <cuda_bf16.h>

// WaveletTransformer_867583394320 — FINAL (converged at machine floor).
//
// Math: 4-level Haar DWT immediately inverted by its exact IDWT with the same
// detail coefficients. Haar is an orthogonal perfect-reconstruction filter
// bank: even = ((xe+xo)+ (xe-xo))*c^2 = 2c^2*xe with c = fp32(0.70710678...),
// so the composed op is x * (2c^2)^4 = x * (1 - ~2.4e-7) elementwise.
// Measured rel_err vs reference: 9.57e-8 (threshold 1e-3). The whole problem
// is an identity => optimal kernel is a pure 256 MiB device-to-device copy.
//
// Bandwidth convergence evidence (all paths, same data):
//   R1  SM float4 grid-stride copy            6361 GB/s   bench 84.5us
//   R2  SM + __ldcs/__stcs + 4x MLP batching  6261 GB/s   bench 84.7us
//   R3  copy-engine memcpy node               ~6.4 TB/s   bench 84.0us
// Three independent engines agree at ~6.3-6.4 TB/s = ~80% of 8 TB/s spec:
// the HBM3e mixed read/write turnaround floor (path-independent chip cap per
// B300_MICROARCH.md). Traffic is irreducible (out==in, disjoint buffers,
// incompressible data), so this is the optimum. Keeping the CE node: fastest
// measured, one graph node, zero kernel-launch overhead, shape-agnostic.

extern "C" void kernel_launch(void* const* d_in, const int* in_sizes, int n_in,
                              void* d_out, int out_size) {
    const float* x = (const float*)d_in[0];
    float* out = (float*)d_out;
    size_t bytes = (size_t)out_size * sizeof(float);
    // Async D2D on the capture (default) stream: captured as a single memcpy
    // node executed by the copy engine. No allocation, no sync — capture-legal.
    cudaMemcpyAsync(out, x, bytes, cudaMemcpyDeviceToDevice, 0);
}